// round 1
// baseline (speedup 1.0000x reference)
#include <cuda_runtime.h>
#include <cstddef>
#include <math.h>

// Ping-pong level buffers (device globals: allocation-free scratch).
// buf0: level0 output = 65536 rows x 256  (also reused by even levels)
// buf1: level1 output = 32768 rows x 256  (reused by odd levels)
__device__ float g_buf0[65536 * 256];
__device__ float g_buf1[32768 * 256];

// ---------- packed f32x2 helpers (Blackwell FFMA2 path) ----------
__device__ __forceinline__ unsigned long long ffma2(unsigned long long a,
                                                    unsigned long long b,
                                                    unsigned long long c) {
    unsigned long long d;
    asm("fma.rn.f32x2 %0, %1, %2, %3;" : "=l"(d) : "l"(a), "l"(b), "l"(c));
    return d;
}
__device__ __forceinline__ unsigned long long dup2(float x) {
    unsigned long long r;
    asm("mov.b64 %0, {%1, %2};" : "=l"(r) : "f"(x), "f"(x));
    return r;
}
__device__ __forceinline__ float2 unpk2(unsigned long long v) {
    float2 r;
    asm("mov.b64 {%0, %1}, %2;" : "=f"(r.x), "=f"(r.y) : "l"(v));
    return r;
}

// A-tile element fetch: either plain row-major read, or fused embedding gather
// (level 0: logical A[m, d] = embed[tokens[b*512 + 2n + (d>>8)]][d & 255]).
__device__ __forceinline__ float4 load_a4(const float* __restrict__ A,
                                          const int* __restrict__ tokens,
                                          const float* __restrict__ embed,
                                          int gather, int m, int col) {
    if (gather) {
        int b = m >> 8;
        int n = m & 255;
        int tok = __ldg(&tokens[(b << 9) + (n << 1) + (col >> 8)]);
        return *reinterpret_cast<const float4*>(embed + (size_t)tok * 256 + (col & 255));
    }
    return *reinterpret_cast<const float4*>(A + (size_t)m * 512 + col);
}

// ---------- level GEMM: out[M,256] = tanh(A[M,512] @ W[256,512]^T + bias) ----------
// Tiles: BM=128, BN=128, BK=16. 256 threads, 8x8 outputs/thread (as 8x4 f32x2).
__global__ void __launch_bounds__(256)
tree_gemm(const float* __restrict__ A,
          const int* __restrict__ tokens,
          const float* __restrict__ embed,
          const float* __restrict__ W,       // [256, 512] row-major (h, d)
          const float* __restrict__ bias,    // [256]
          float* __restrict__ out,           // [M, 256]
          int M, int gather) {
    __shared__ float As[16][132];  // transposed A tile: As[k][m], padded
    __shared__ float Bs[16][132];  // transposed W tile: Bs[k][n], padded

    const int tid = threadIdx.x;
    const int tm = tid >> 4;       // 0..15 -> rows tm*8 .. tm*8+7
    const int tn = tid & 15;       // 0..15 -> cols tn*8 .. tn*8+7
    const int rowBase = blockIdx.x * 128;
    const int nBase   = blockIdx.y * 128;

    // Cooperative load mapping: each thread loads 2 float4 per tile
    const int r0  = tid >> 2;        // 0..63 (and r0+64)
    const int cq0 = (tid & 3) << 2;  // k-offset within BK: 0,4,8,12

    unsigned long long acc[8][4];
#pragma unroll
    for (int i = 0; i < 8; ++i)
#pragma unroll
        for (int j = 0; j < 4; ++j) acc[i][j] = 0ull;

    // prefetch stage 0
    float4 pa0 = load_a4(A, tokens, embed, gather, rowBase + r0,      cq0);
    float4 pa1 = load_a4(A, tokens, embed, gather, rowBase + r0 + 64, cq0);
    float4 pb0 = *reinterpret_cast<const float4*>(W + (size_t)(nBase + r0)      * 512 + cq0);
    float4 pb1 = *reinterpret_cast<const float4*>(W + (size_t)(nBase + r0 + 64) * 512 + cq0);

    for (int kt = 0; kt < 32; ++kt) {
        // commit prefetched tile to smem (transposed)
        As[cq0 + 0][r0] = pa0.x; As[cq0 + 1][r0] = pa0.y;
        As[cq0 + 2][r0] = pa0.z; As[cq0 + 3][r0] = pa0.w;
        As[cq0 + 0][r0 + 64] = pa1.x; As[cq0 + 1][r0 + 64] = pa1.y;
        As[cq0 + 2][r0 + 64] = pa1.z; As[cq0 + 3][r0 + 64] = pa1.w;
        Bs[cq0 + 0][r0] = pb0.x; Bs[cq0 + 1][r0] = pb0.y;
        Bs[cq0 + 2][r0] = pb0.z; Bs[cq0 + 3][r0] = pb0.w;
        Bs[cq0 + 0][r0 + 64] = pb1.x; Bs[cq0 + 1][r0 + 64] = pb1.y;
        Bs[cq0 + 2][r0 + 64] = pb1.z; Bs[cq0 + 3][r0 + 64] = pb1.w;
        __syncthreads();

        if (kt + 1 < 32) {
            int k0 = (kt + 1) << 4;
            pa0 = load_a4(A, tokens, embed, gather, rowBase + r0,      k0 + cq0);
            pa1 = load_a4(A, tokens, embed, gather, rowBase + r0 + 64, k0 + cq0);
            pb0 = *reinterpret_cast<const float4*>(W + (size_t)(nBase + r0)      * 512 + k0 + cq0);
            pb1 = *reinterpret_cast<const float4*>(W + (size_t)(nBase + r0 + 64) * 512 + k0 + cq0);
        }

#pragma unroll
        for (int kk = 0; kk < 16; ++kk) {
            // a: 8 rows (broadcast within pair via dup2)
            float4 a0 = *reinterpret_cast<const float4*>(&As[kk][tm * 8]);
            float4 a1 = *reinterpret_cast<const float4*>(&As[kk][tm * 8 + 4]);
            unsigned long long ap[8];
            ap[0] = dup2(a0.x); ap[1] = dup2(a0.y); ap[2] = dup2(a0.z); ap[3] = dup2(a0.w);
            ap[4] = dup2(a1.x); ap[5] = dup2(a1.y); ap[6] = dup2(a1.z); ap[7] = dup2(a1.w);
            // b: 4 n-pairs, loaded directly as 64-bit from smem
            const unsigned long long* brow =
                reinterpret_cast<const unsigned long long*>(&Bs[kk][tn * 8]);
            unsigned long long bp0 = brow[0], bp1 = brow[1], bp2 = brow[2], bp3 = brow[3];
#pragma unroll
            for (int i = 0; i < 8; ++i) {
                acc[i][0] = ffma2(ap[i], bp0, acc[i][0]);
                acc[i][1] = ffma2(ap[i], bp1, acc[i][1]);
                acc[i][2] = ffma2(ap[i], bp2, acc[i][2]);
                acc[i][3] = ffma2(ap[i], bp3, acc[i][3]);
            }
        }
        __syncthreads();
    }

    // epilogue: + bias, tanh, vectorized store
    float bl[8];
#pragma unroll
    for (int j = 0; j < 8; ++j) bl[j] = bias[nBase + tn * 8 + j];

#pragma unroll
    for (int i = 0; i < 8; ++i) {
        int m = rowBase + tm * 8 + i;
        float2 v0 = unpk2(acc[i][0]);
        float2 v1 = unpk2(acc[i][1]);
        float2 v2 = unpk2(acc[i][2]);
        float2 v3 = unpk2(acc[i][3]);
        float4 o0, o1;
        o0.x = tanhf(v0.x + bl[0]); o0.y = tanhf(v0.y + bl[1]);
        o0.z = tanhf(v1.x + bl[2]); o0.w = tanhf(v1.y + bl[3]);
        o1.x = tanhf(v2.x + bl[4]); o1.y = tanhf(v2.y + bl[5]);
        o1.z = tanhf(v3.x + bl[6]); o1.w = tanhf(v3.y + bl[7]);
        float* orow = out + (size_t)m * 256 + nBase + tn * 8;
        *reinterpret_cast<float4*>(orow)     = o0;
        *reinterpret_cast<float4*>(orow + 4) = o1;
    }
}

// ---------- head: hidden = relu(root @ WF^T + bF); out = hidden @ WO^T + bO ----------
__global__ void __launch_bounds__(256)
head_kernel(const float* __restrict__ root,  // [256, 256]
            const float* __restrict__ WF,    // [256, 256]
            const float* __restrict__ bF,    // [256]
            const float* __restrict__ WO,    // [5, 256]
            const float* __restrict__ bO,    // [5]
            float* __restrict__ out) {       // [256, 5]
    __shared__ float r[256];
    __shared__ float h[256];
    int b = blockIdx.x, t = threadIdx.x;
    r[t] = root[b * 256 + t];
    __syncthreads();
    float acc = bF[t];
    const float* w = WF + (size_t)t * 256;
#pragma unroll 8
    for (int d = 0; d < 256; d += 4) {
        float4 w4 = *reinterpret_cast<const float4*>(w + d);
        acc += r[d] * w4.x + r[d + 1] * w4.y + r[d + 2] * w4.z + r[d + 3] * w4.w;
    }
    h[t] = fmaxf(acc, 0.0f);
    __syncthreads();
    int wid = t >> 5, lane = t & 31;
    if (wid < 5) {
        float s = 0.0f;
        for (int i = lane; i < 256; i += 32) s += h[i] * WO[wid * 256 + i];
#pragma unroll
        for (int o = 16; o; o >>= 1) s += __shfl_down_sync(0xffffffffu, s, o);
        if (lane == 0) out[b * 5 + wid] = s + bO[wid];
    }
}

extern "C" void kernel_launch(void* const* d_in, const int* in_sizes, int n_in,
                              void* d_out, int out_size) {
    (void)in_sizes; (void)n_in; (void)out_size;
    const int*   tokens = (const int*)  d_in[0];
    const float* embed  = (const float*)d_in[1];
    const float* WR_w   = (const float*)d_in[2];
    const float* WR_b   = (const float*)d_in[3];
    const float* WF_w   = (const float*)d_in[4];
    const float* WF_b   = (const float*)d_in[5];
    const float* WO_w   = (const float*)d_in[6];
    const float* WO_b   = (const float*)d_in[7];
    float* out = (float*)d_out;

    float *buf0 = nullptr, *buf1 = nullptr;
    cudaGetSymbolAddress((void**)&buf0, g_buf0);
    cudaGetSymbolAddress((void**)&buf1, g_buf1);

    dim3 block(256);

    // level 0: fused embedding gather, M = 65536
    {
        dim3 grid(65536 / 128, 2);
        tree_gemm<<<grid, block>>>(nullptr, tokens, embed, WR_w, WR_b, buf0, 65536, 1);
    }
    // levels 1..8: ping-pong
    float* src = buf0;
    float* dst = buf1;
    for (int k = 1; k <= 8; ++k) {
        int M = 65536 >> k;
        dim3 grid(M / 128, 2);
        tree_gemm<<<grid, block>>>(src, nullptr, nullptr, WR_w, WR_b, dst, M, 0);
        float* tmp = src; src = dst; dst = tmp;
    }
    // src now holds the root vectors [256, 256]
    head_kernel<<<256, block>>>(src, WF_w, WF_b, WO_w, WO_b, out);
}

// round 3
// speedup vs baseline: 1.9299x; 1.9299x over previous
#include <cuda_runtime.h>
#include <cuda_bf16.h>
#include <cstdint>
#include <cstddef>
#include <math.h>

// ======================= device-global scratch (no allocs allowed) =======================
__device__ __align__(256) __nv_bfloat16 g_Ahi[33554432];  // 65536 x 512
__device__ __align__(256) __nv_bfloat16 g_Alo[33554432];
__device__ __align__(256) __nv_bfloat16 g_Bhi[16777216];  // 65536 x 256
__device__ __align__(256) __nv_bfloat16 g_Blo[16777216];
__device__ __align__(256) __nv_bfloat16 g_Whi[131072];    // WR_w hi [256,512]
__device__ __align__(256) __nv_bfloat16 g_Wlo[131072];    // WR_w lo

// ======================= helpers =======================
__device__ __forceinline__ uint32_t smem_u32(const void* p) {
    uint32_t a;
    asm("{ .reg .u64 t; cvta.to.shared.u64 t, %1; cvt.u32.u64 %0, t; }" : "=r"(a) : "l"(p));
    return a;
}
__device__ __forceinline__ void cpa16(uint32_t dst, const void* src) {
    asm volatile("cp.async.cg.shared.global [%0], [%1], 16;" :: "r"(dst), "l"(src));
}
#define CP_COMMIT() asm volatile("cp.async.commit_group;" ::: "memory")
#define CP_WAIT(n)  asm volatile("cp.async.wait_group %0;" :: "n"(n) : "memory")

__device__ __forceinline__ void mma16816(float* c, const uint32_t* a, const uint32_t* b) {
    asm volatile(
        "mma.sync.aligned.m16n8k16.row.col.f32.bf16.bf16.f32 "
        "{%0,%1,%2,%3}, {%4,%5,%6,%7}, {%8,%9}, {%0,%1,%2,%3};"
        : "+f"(c[0]), "+f"(c[1]), "+f"(c[2]), "+f"(c[3])
        : "r"(a[0]), "r"(a[1]), "r"(a[2]), "r"(a[3]), "r"(b[0]), "r"(b[1]));
}

// ======================= level GEMM (mma.sync bf16-split) =======================
// out[M,256] = tanh(A[M,512] @ W[256,512]^T + bias), written as bf16 hi/lo pair.
// CTA tile 128x128, 8 warps (4 along M x 2 along N), warp tile 32x64.
// KC=32 k-chunk, 2-stage cp.async double buffer.
// SMEM per stage: Ahi|Alo|Bhi|Blo, each 128 rows x 32 bf16, row stride 80B.
static constexpr int BM = 128, BN = 128, KC = 32;
static constexpr int NCH = 512 / KC;             // 16 chunks
static constexpr int RSTRIDE = 80;               // 64B data + 16B pad (16B-aligned)
static constexpr int TILE_B = 128 * RSTRIDE;     // 10240 B
static constexpr int STAGE_B = 4 * TILE_B;       // 40960 B
static constexpr int SMEM_BYTES = 2 * STAGE_B;   // 81920 B

__global__ void __launch_bounds__(256)
mma_level(const __nv_bfloat16* __restrict__ Ahi, const __nv_bfloat16* __restrict__ Alo,
          const float* __restrict__ bias,
          __nv_bfloat16* __restrict__ Ohi, __nv_bfloat16* __restrict__ Olo) {
    extern __shared__ char sm[];
    const uint32_t smb = smem_u32(sm);

    const int tid  = threadIdx.x;
    const int wid  = tid >> 5;
    const int lane = tid & 31;
    const int g    = lane >> 2;      // group id 0..7
    const int t    = lane & 3;       // thread-in-group 0..3
    const int warp_m = wid & 3;      // 4 warps along M (32 rows each)
    const int warp_n = wid >> 2;     // 2 warps along N (64 cols each)
    const int m0 = warp_m * 32;
    const int n0 = warp_n * 64;
    const int rowBase = blockIdx.x * BM;
    const int nBase   = blockIdx.y * BN;

    // ---- chunk fill: 2048 cp.async of 16B, 8 per thread ----
    auto fill = [&](int c, int s) {
        const uint32_t sb = smb + s * STAGE_B;
#pragma unroll
        for (int i = 0; i < 8; ++i) {
            int o   = tid + i * 256;     // 0..2047
            int op  = o >> 9;            // 0:Ahi 1:Alo 2:Bhi 3:Blo  (512 units each)
            int idx = o & 511;
            int r   = idx >> 2;          // 0..127
            int u   = idx & 3;           // 16B unit within 64B row
            const __nv_bfloat16* src;
            int grow;
            if (op < 2) { src = op ? Alo : Ahi; grow = rowBase + r; }
            else        { src = (op == 2) ? g_Whi : g_Wlo; grow = nBase + r; }
            const void* gp = src + (size_t)grow * 512 + c * KC + u * 8;
            cpa16(sb + op * TILE_B + r * RSTRIDE + u * 16, gp);
        }
        CP_COMMIT();
    };

    float acc[2][8][4];
#pragma unroll
    for (int mt = 0; mt < 2; ++mt)
#pragma unroll
        for (int nt = 0; nt < 8; ++nt)
#pragma unroll
            for (int j = 0; j < 4; ++j) acc[mt][nt][j] = 0.0f;

    fill(0, 0);

    for (int c = 0; c < NCH; ++c) {
        if (c + 1 < NCH) { fill(c + 1, (c + 1) & 1); CP_WAIT(1); }
        else             { CP_WAIT(0); }
        __syncthreads();

        const uint32_t sb  = smb + (c & 1) * STAGE_B;
        const uint32_t SAh = sb + 0 * TILE_B;
        const uint32_t SAl = sb + 1 * TILE_B;
        const uint32_t SBh = sb + 2 * TILE_B;
        const uint32_t SBl = sb + 3 * TILE_B;

#pragma unroll
        for (int ks = 0; ks < 2; ++ks) {          // two k16 steps in KC=32
            const int kb = ks * 32 + t * 4;       // byte offset of col pair 2t in this k16

            uint32_t Ah[2][4], Al[2][4];
#pragma unroll
            for (int mt = 0; mt < 2; ++mt) {
                const uint32_t ra = (uint32_t)(m0 + mt * 16 + g) * RSTRIDE + kb;
                asm volatile("ld.shared.b32 %0, [%1];"      : "=r"(Ah[mt][0]) : "r"(SAh + ra));
                asm volatile("ld.shared.b32 %0, [%1];"      : "=r"(Ah[mt][1]) : "r"(SAh + ra + 8 * RSTRIDE));
                asm volatile("ld.shared.b32 %0, [%1];"      : "=r"(Ah[mt][2]) : "r"(SAh + ra + 16));
                asm volatile("ld.shared.b32 %0, [%1];"      : "=r"(Ah[mt][3]) : "r"(SAh + ra + 8 * RSTRIDE + 16));
                asm volatile("ld.shared.b32 %0, [%1];"      : "=r"(Al[mt][0]) : "r"(SAl + ra));
                asm volatile("ld.shared.b32 %0, [%1];"      : "=r"(Al[mt][1]) : "r"(SAl + ra + 8 * RSTRIDE));
                asm volatile("ld.shared.b32 %0, [%1];"      : "=r"(Al[mt][2]) : "r"(SAl + ra + 16));
                asm volatile("ld.shared.b32 %0, [%1];"      : "=r"(Al[mt][3]) : "r"(SAl + ra + 8 * RSTRIDE + 16));
            }

#pragma unroll
            for (int nt = 0; nt < 8; ++nt) {
                const uint32_t rb = (uint32_t)(n0 + nt * 8 + g) * RSTRIDE + kb;
                uint32_t Bh[2], Bl[2];
                asm volatile("ld.shared.b32 %0, [%1];" : "=r"(Bh[0]) : "r"(SBh + rb));
                asm volatile("ld.shared.b32 %0, [%1];" : "=r"(Bh[1]) : "r"(SBh + rb + 16));
                asm volatile("ld.shared.b32 %0, [%1];" : "=r"(Bl[0]) : "r"(SBl + rb));
                asm volatile("ld.shared.b32 %0, [%1];" : "=r"(Bl[1]) : "r"(SBl + rb + 16));
#pragma unroll
                for (int mt = 0; mt < 2; ++mt) {
                    mma16816(acc[mt][nt], Ah[mt], Bh);
                    mma16816(acc[mt][nt], Ah[mt], Bl);
                    mma16816(acc[mt][nt], Al[mt], Bh);
                }
            }
        }
        __syncthreads();
    }

    // ---- epilogue: +bias, tanh, bf16 hi/lo split, store ----
#pragma unroll
    for (int mt = 0; mt < 2; ++mt) {
#pragma unroll
        for (int nt = 0; nt < 8; ++nt) {
            const int col = nBase + n0 + nt * 8 + 2 * t;
            const float b0 = __ldg(&bias[col]);
            const float b1 = __ldg(&bias[col + 1]);
#pragma unroll
            for (int h = 0; h < 2; ++h) {      // c0,c1 (row +g) / c2,c3 (row +g+8)
                const int row = rowBase + m0 + mt * 16 + g + h * 8;
                float v0 = tanhf(acc[mt][nt][2 * h]     + b0);
                float v1 = tanhf(acc[mt][nt][2 * h + 1] + b1);
                __nv_bfloat16 h0 = __float2bfloat16(v0);
                __nv_bfloat16 h1 = __float2bfloat16(v1);
                __nv_bfloat162 hp; hp.x = h0; hp.y = h1;
                __nv_bfloat162 lp;
                lp.x = __float2bfloat16(v0 - __bfloat162float(h0));
                lp.y = __float2bfloat16(v1 - __bfloat162float(h1));
                *reinterpret_cast<__nv_bfloat162*>(Ohi + (size_t)row * 256 + col) = hp;
                *reinterpret_cast<__nv_bfloat162*>(Olo + (size_t)row * 256 + col) = lp;
            }
        }
    }
}

// ======================= level-0 gather + bf16 hi/lo split =======================
// A0[m, d] = embed[ tokens[(m>>8)*512 + (m&255)*2 + (d>>8)] ][ d&255 ],  m in [0,65536)
__global__ void __launch_bounds__(256)
gather_split(const int* __restrict__ tokens, const float* __restrict__ embed) {
    int unit = blockIdx.x * 256 + threadIdx.x;     // 4194304 units of 8 elems
    int m    = unit >> 6;
    int pos  = (unit & 63) * 8;
    int tok  = __ldg(&tokens[((m >> 8) << 9) + ((m & 255) << 1) + (pos >> 8)]);
    const float4* src = reinterpret_cast<const float4*>(embed + (size_t)tok * 256 + (pos & 255));
    float4 v0 = src[0], v1 = src[1];
    float v[8] = {v0.x, v0.y, v0.z, v0.w, v1.x, v1.y, v1.z, v1.w};
    uint32_t hw[4], lw[4];
#pragma unroll
    for (int j = 0; j < 4; ++j) {
        __nv_bfloat16 h0 = __float2bfloat16(v[2 * j]);
        __nv_bfloat16 h1 = __float2bfloat16(v[2 * j + 1]);
        __nv_bfloat162 h2; h2.x = h0; h2.y = h1;
        __nv_bfloat162 l2;
        l2.x = __float2bfloat16(v[2 * j]     - __bfloat162float(h0));
        l2.y = __float2bfloat16(v[2 * j + 1] - __bfloat162float(h1));
        hw[j] = *reinterpret_cast<uint32_t*>(&h2);
        lw[j] = *reinterpret_cast<uint32_t*>(&l2);
    }
    size_t off = (size_t)m * 512 + pos;
    *reinterpret_cast<uint4*>(g_Ahi + off) = make_uint4(hw[0], hw[1], hw[2], hw[3]);
    *reinterpret_cast<uint4*>(g_Alo + off) = make_uint4(lw[0], lw[1], lw[2], lw[3]);
}

// ======================= weight split =======================
__global__ void __launch_bounds__(256)
weight_split(const float* __restrict__ W) {
    int i = blockIdx.x * 256 + threadIdx.x;        // 131072 elems
    float v = W[i];
    __nv_bfloat16 h = __float2bfloat16(v);
    g_Whi[i] = h;
    g_Wlo[i] = __float2bfloat16(v - __bfloat162float(h));
}

// ======================= head =======================
__global__ void __launch_bounds__(256)
head_kernel(const __nv_bfloat16* __restrict__ rootH, const __nv_bfloat16* __restrict__ rootL,
            const float* __restrict__ WF, const float* __restrict__ bF,
            const float* __restrict__ WO, const float* __restrict__ bO,
            float* __restrict__ out) {
    __shared__ float r[256];
    __shared__ float h[256];
    int b = blockIdx.x, t = threadIdx.x;
    r[t] = __bfloat162float(rootH[b * 256 + t]) + __bfloat162float(rootL[b * 256 + t]);
    __syncthreads();
    float acc = bF[t];
    const float* w = WF + (size_t)t * 256;
#pragma unroll 8
    for (int d = 0; d < 256; d += 4) {
        float4 w4 = *reinterpret_cast<const float4*>(w + d);
        acc += r[d] * w4.x + r[d + 1] * w4.y + r[d + 2] * w4.z + r[d + 3] * w4.w;
    }
    h[t] = fmaxf(acc, 0.0f);
    __syncthreads();
    int wid = t >> 5, lane = t & 31;
    if (wid < 5) {
        float s = 0.0f;
        for (int i = lane; i < 256; i += 32) s += h[i] * WO[wid * 256 + i];
#pragma unroll
        for (int o = 16; o; o >>= 1) s += __shfl_down_sync(0xffffffffu, s, o);
        if (lane == 0) out[b * 5 + wid] = s + bO[wid];
    }
}

// ======================= launch =======================
extern "C" void kernel_launch(void* const* d_in, const int* in_sizes, int n_in,
                              void* d_out, int out_size) {
    (void)in_sizes; (void)n_in; (void)out_size;
    const int*   tokens = (const int*)  d_in[0];
    const float* embed  = (const float*)d_in[1];
    const float* WR_w   = (const float*)d_in[2];
    const float* WR_b   = (const float*)d_in[3];
    const float* WF_w   = (const float*)d_in[4];
    const float* WF_b   = (const float*)d_in[5];
    const float* WO_w   = (const float*)d_in[6];
    const float* WO_b   = (const float*)d_in[7];
    float* out = (float*)d_out;

    cudaFuncSetAttribute(mma_level, cudaFuncAttributeMaxDynamicSharedMemorySize, SMEM_BYTES);

    __nv_bfloat16 *Ahi, *Alo, *Bhi, *Blo;
    cudaGetSymbolAddress((void**)&Ahi, g_Ahi);
    cudaGetSymbolAddress((void**)&Alo, g_Alo);
    cudaGetSymbolAddress((void**)&Bhi, g_Bhi);
    cudaGetSymbolAddress((void**)&Blo, g_Blo);

    weight_split<<<512, 256>>>(WR_w);
    gather_split<<<16384, 256>>>(tokens, embed);

    for (int lvl = 0; lvl < 9; ++lvl) {
        int M = 65536 >> lvl;                       // output rows of this level
        const __nv_bfloat16 *iH, *iL;
        __nv_bfloat16 *oH, *oL;
        if ((lvl & 1) == 0) { iH = Ahi; iL = Alo; oH = Bhi; oL = Blo; }
        else                { iH = Bhi; iL = Blo; oH = Ahi; oL = Alo; }
        dim3 grid(M / BM, 2);
        mma_level<<<grid, 256, SMEM_BYTES>>>(iH, iL, WR_b, oH, oL);
    }
    // final (lvl 8) output landed in B buffers: [256, 256]
    head_kernel<<<256, 256>>>(Bhi, Blo, WF_w, WF_b, WO_w, WO_b, out);
}

// round 4
// speedup vs baseline: 2.9216x; 1.5139x over previous
#include <cuda_runtime.h>
#include <cuda_fp16.h>
#include <cstdint>
#include <cstddef>
#include <math.h>

// ======================= device-global scratch (no allocs allowed) =======================
__device__ __align__(256) __half g_A[16777216];   // activations ping (fp16 hi), 65536x256 max
__device__ __align__(256) __half g_B[16777216];   // activations pong
__device__ __align__(256) __half g_Wh[131072];    // WR_w hi  [256,512]
__device__ __align__(256) __half g_Wl[131072];    // WR_w lo  [256,512]

// ======================= helpers =======================
__device__ __forceinline__ uint32_t smem_u32(const void* p) {
    uint32_t a;
    asm("{ .reg .u64 t; cvta.to.shared.u64 t, %1; cvt.u32.u64 %0, t; }" : "=r"(a) : "l"(p));
    return a;
}
__device__ __forceinline__ void cpa16(uint32_t dst, const void* src) {
    asm volatile("cp.async.cg.shared.global [%0], [%1], 16;" :: "r"(dst), "l"(src));
}
#define CP_COMMIT() asm volatile("cp.async.commit_group;" ::: "memory")
#define CP_WAIT(n)  asm volatile("cp.async.wait_group %0;" :: "n"(n) : "memory")

#define LDSM4(r0, r1, r2, r3, a) \
    asm volatile("ldmatrix.sync.aligned.m8n8.x4.shared.b16 {%0,%1,%2,%3}, [%4];" \
                 : "=r"(r0), "=r"(r1), "=r"(r2), "=r"(r3) : "r"(a))

__device__ __forceinline__ void mma16816(float* c, const uint32_t* a, uint32_t b0, uint32_t b1) {
    asm volatile(
        "mma.sync.aligned.m16n8k16.row.col.f32.f16.f16.f32 "
        "{%0,%1,%2,%3}, {%4,%5,%6,%7}, {%8,%9}, {%0,%1,%2,%3};"
        : "+f"(c[0]), "+f"(c[1]), "+f"(c[2]), "+f"(c[3])
        : "r"(a[0]), "r"(a[1]), "r"(a[2]), "r"(a[3]), "r"(b0), "r"(b1));
}

// ======================= level GEMM (mma.sync fp16, W split hi/lo) =======================
// out[M,256] = tanh(A[M,512] @ W[256,512]^T + bias), fp16 output (hi only).
// D = Ah*Wh + Ah*Wl  (A rounded once to fp16; W exact to ~2^-22).
// CTA 128x128, 8 warps (4 M x 2 N), warp tile 32x64. KC=32, 3-stage cp.async ring.
static constexpr int BM = 128, BN = 128, KC = 32;
static constexpr int NCH = 512 / KC;            // 16 chunks
static constexpr int RSTRIDE = 80;              // 64B data + 16B pad; conflict-free
static constexpr int A_B = 128 * RSTRIDE;       // 10240 B
static constexpr int W_B = 128 * RSTRIDE;       // 10240 B
static constexpr int STAGE_B = A_B + 2 * W_B;   // 30720 B
static constexpr int NSTG = 3;
static constexpr int SMEM_BYTES = NSTG * STAGE_B;  // 92160 B -> 2 CTAs/SM

__device__ __forceinline__ uint32_t laddr(uint32_t S, int base_row, int ks, int lane) {
    return S + (uint32_t)(base_row + (lane & 15)) * RSTRIDE + ks * 32 + ((lane >> 4) << 4);
}

template <bool GATHER>
__global__ void __launch_bounds__(256, 2)
mma_level(const __half* __restrict__ Ain,
          const int* __restrict__ tokens, const float* __restrict__ embed,
          const float* __restrict__ bias, __half* __restrict__ Out) {
    extern __shared__ char sm[];
    const uint32_t smb = smem_u32(sm);

    const int tid  = threadIdx.x;
    const int wid  = tid >> 5;
    const int lane = tid & 31;
    const int g    = lane >> 2;
    const int t    = lane & 3;
    const int m0 = (wid & 3) * 32;
    const int n0 = (wid >> 2) * 64;
    const int rowBase = blockIdx.x * BM;
    const int nBase   = blockIdx.y * BN;

    auto fill = [&](int c, int s) {
        const uint32_t sb = smb + s * STAGE_B;
        if (GATHER) {
#pragma unroll
            for (int i = 0; i < 2; ++i) {            // 512 A units, 2/thread
                int o = tid + i * 256;
                int r = o >> 2, u = o & 3;
                int m  = rowBase + r;
                int d0 = c * KC + u * 8;
                int tok = __ldg(&tokens[((m >> 8) << 9) + ((m & 255) << 1) + (d0 >> 8)]);
                const float4* src =
                    reinterpret_cast<const float4*>(embed + (size_t)tok * 256 + (d0 & 255));
                float4 v0 = src[0], v1 = src[1];
                __half2 h0 = __floats2half2_rn(v0.x, v0.y);
                __half2 h1 = __floats2half2_rn(v0.z, v0.w);
                __half2 h2 = __floats2half2_rn(v1.x, v1.y);
                __half2 h3 = __floats2half2_rn(v1.z, v1.w);
                uint4 pk;
                pk.x = *reinterpret_cast<uint32_t*>(&h0);
                pk.y = *reinterpret_cast<uint32_t*>(&h1);
                pk.z = *reinterpret_cast<uint32_t*>(&h2);
                pk.w = *reinterpret_cast<uint32_t*>(&h3);
                *reinterpret_cast<uint4*>(sm + s * STAGE_B + r * RSTRIDE + u * 16) = pk;
            }
        } else {
#pragma unroll
            for (int i = 0; i < 2; ++i) {
                int o = tid + i * 256;
                int r = o >> 2, u = o & 3;
                cpa16(sb + r * RSTRIDE + u * 16,
                      Ain + (size_t)(rowBase + r) * 512 + c * KC + u * 8);
            }
        }
#pragma unroll
        for (int i = 0; i < 4; ++i) {               // 1024 W units (hi then lo)
            int o  = tid + i * 256;
            int op = o >> 9;                        // 0: Wh, 1: Wl
            int idx = o & 511;
            int r = idx >> 2, u = idx & 3;
            const __half* src = op ? g_Wl : g_Wh;
            cpa16(sb + A_B + op * W_B + r * RSTRIDE + u * 16,
                  src + (size_t)(nBase + r) * 512 + c * KC + u * 8);
        }
        CP_COMMIT();
    };

    float acc[2][8][4];
#pragma unroll
    for (int mt = 0; mt < 2; ++mt)
#pragma unroll
        for (int nt = 0; nt < 8; ++nt)
#pragma unroll
            for (int j = 0; j < 4; ++j) acc[mt][nt][j] = 0.0f;

    fill(0, 0);
    fill(1, 1);

    for (int c = 0; c < NCH; ++c) {
        if (c < NCH - 1) { CP_WAIT(1); } else { CP_WAIT(0); }
        __syncthreads();
        if (c + 2 < NCH) fill(c + 2, (c + 2) % NSTG);   // stage (c-1)%NSTG: readers done

        const uint32_t sb  = smb + (c % NSTG) * STAGE_B;
        const uint32_t SA  = sb;
        const uint32_t SWh = sb + A_B;
        const uint32_t SWl = sb + A_B + W_B;

#pragma unroll
        for (int ks = 0; ks < 2; ++ks) {
            uint32_t a[2][4];
            LDSM4(a[0][0], a[0][1], a[0][2], a[0][3], laddr(SA, m0, ks, lane));
            LDSM4(a[1][0], a[1][1], a[1][2], a[1][3], laddr(SA, m0 + 16, ks, lane));
#pragma unroll
            for (int half = 0; half < 2; ++half) {
                uint32_t bh[8], bl[8];
                LDSM4(bh[0], bh[1], bh[2], bh[3], laddr(SWh, n0 + half * 32,      ks, lane));
                LDSM4(bh[4], bh[5], bh[6], bh[7], laddr(SWh, n0 + half * 32 + 16, ks, lane));
                LDSM4(bl[0], bl[1], bl[2], bl[3], laddr(SWl, n0 + half * 32,      ks, lane));
                LDSM4(bl[4], bl[5], bl[6], bl[7], laddr(SWl, n0 + half * 32 + 16, ks, lane));
#pragma unroll
                for (int jj = 0; jj < 2; ++jj) {
#pragma unroll
                    for (int sub = 0; sub < 2; ++sub) {
                        const int nt = half * 4 + jj * 2 + sub;
                        const uint32_t bh0 = bh[jj * 4 + sub], bh1 = bh[jj * 4 + sub + 2];
                        const uint32_t bl0 = bl[jj * 4 + sub], bl1 = bl[jj * 4 + sub + 2];
                        mma16816(acc[0][nt], a[0], bh0, bh1);
                        mma16816(acc[1][nt], a[1], bh0, bh1);
                        mma16816(acc[0][nt], a[0], bl0, bl1);
                        mma16816(acc[1][nt], a[1], bl0, bl1);
                    }
                }
            }
        }
    }

    // ---- epilogue: +bias, tanh, fp16 store ----
#pragma unroll
    for (int mt = 0; mt < 2; ++mt) {
#pragma unroll
        for (int nt = 0; nt < 8; ++nt) {
            const int col = nBase + n0 + nt * 8 + 2 * t;
            const float b0 = __ldg(&bias[col]);
            const float b1 = __ldg(&bias[col + 1]);
#pragma unroll
            for (int h = 0; h < 2; ++h) {
                const int row = rowBase + m0 + mt * 16 + g + h * 8;
                float v0 = tanhf(acc[mt][nt][2 * h]     + b0);
                float v1 = tanhf(acc[mt][nt][2 * h + 1] + b1);
                *reinterpret_cast<__half2*>(Out + (size_t)row * 256 + col) =
                    __floats2half2_rn(v0, v1);
            }
        }
    }
}

// ======================= weight split =======================
__global__ void __launch_bounds__(256)
weight_split(const float* __restrict__ W) {
    int i = blockIdx.x * 256 + threadIdx.x;        // 131072 elems
    float v = W[i];
    __half h = __float2half_rn(v);
    g_Wh[i] = h;
    g_Wl[i] = __float2half_rn(v - __half2float(h));
}

// ======================= head =======================
__global__ void __launch_bounds__(256)
head_kernel(const __half* __restrict__ root,      // [256, 256] fp16
            const float* __restrict__ WF, const float* __restrict__ bF,
            const float* __restrict__ WO, const float* __restrict__ bO,
            float* __restrict__ out) {
    __shared__ float r[256];
    __shared__ float h[256];
    int b = blockIdx.x, t = threadIdx.x;
    r[t] = __half2float(root[b * 256 + t]);
    __syncthreads();
    float acc = bF[t];
    const float* w = WF + (size_t)t * 256;
#pragma unroll 8
    for (int d = 0; d < 256; d += 4) {
        float4 w4 = *reinterpret_cast<const float4*>(w + d);
        acc += r[d] * w4.x + r[d + 1] * w4.y + r[d + 2] * w4.z + r[d + 3] * w4.w;
    }
    h[t] = fmaxf(acc, 0.0f);
    __syncthreads();
    int wid = t >> 5, lane = t & 31;
    if (wid < 5) {
        float s = 0.0f;
        for (int i = lane; i < 256; i += 32) s += h[i] * WO[wid * 256 + i];
#pragma unroll
        for (int o = 16; o; o >>= 1) s += __shfl_down_sync(0xffffffffu, s, o);
        if (lane == 0) out[b * 5 + wid] = s + bO[wid];
    }
}

// ======================= launch =======================
extern "C" void kernel_launch(void* const* d_in, const int* in_sizes, int n_in,
                              void* d_out, int out_size) {
    (void)in_sizes; (void)n_in; (void)out_size;
    const int*   tokens = (const int*)  d_in[0];
    const float* embed  = (const float*)d_in[1];
    const float* WR_w   = (const float*)d_in[2];
    const float* WR_b   = (const float*)d_in[3];
    const float* WF_w   = (const float*)d_in[4];
    const float* WF_b   = (const float*)d_in[5];
    const float* WO_w   = (const float*)d_in[6];
    const float* WO_b   = (const float*)d_in[7];
    float* out = (float*)d_out;

    cudaFuncSetAttribute(mma_level<true>,  cudaFuncAttributeMaxDynamicSharedMemorySize, SMEM_BYTES);
    cudaFuncSetAttribute(mma_level<false>, cudaFuncAttributeMaxDynamicSharedMemorySize, SMEM_BYTES);

    __half *A, *B;
    cudaGetSymbolAddress((void**)&A, g_A);
    cudaGetSymbolAddress((void**)&B, g_B);

    weight_split<<<512, 256>>>(WR_w);

    // level 0: fused embedding gather, M = 65536, out -> g_A
    {
        dim3 grid(65536 / BM, 2);
        mma_level<true><<<grid, 256, SMEM_BYTES>>>(nullptr, tokens, embed, WR_b, A);
    }
    // levels 1..8: ping-pong  (lvl odd: A->B, lvl even: B->A)
    for (int lvl = 1; lvl <= 8; ++lvl) {
        int M = 65536 >> lvl;
        dim3 grid(M / BM, 2);
        const __half* in = (lvl & 1) ? A : B;
        __half*       ot = (lvl & 1) ? B : A;
        mma_level<false><<<grid, 256, SMEM_BYTES>>>(in, nullptr, nullptr, WR_b, ot);
    }
    // root in g_A: [256, 256]
    head_kernel<<<256, 256>>>(A, WF_w, WF_b, WO_w, WO_b, out);
}

// round 5
// speedup vs baseline: 4.6602x; 1.5951x over previous
#include <cuda_runtime.h>
#include <cuda_fp16.h>
#include <cstdint>
#include <cstddef>
#include <math.h>

// ======================= device-global scratch (no allocs allowed) =======================
__device__ __align__(256) __half g_A[16777216];   // activations ping, 65536x256 max
__device__ __align__(256) __half g_B[16777216];   // activations pong
__device__ __align__(256) __half g_W[131072];     // WR_w fp16 [256,512]
__device__ __align__(256) __half g_E[8192000];    // embed table fp16 [32000,256]

// ======================= helpers =======================
__device__ __forceinline__ uint32_t smem_u32(const void* p) {
    uint32_t a;
    asm("{ .reg .u64 t; cvta.to.shared.u64 t, %1; cvt.u32.u64 %0, t; }" : "=r"(a) : "l"(p));
    return a;
}
__device__ __forceinline__ void cpa16(uint32_t dst, const void* src) {
    asm volatile("cp.async.cg.shared.global [%0], [%1], 16;" :: "r"(dst), "l"(src));
}
#define CP_COMMIT() asm volatile("cp.async.commit_group;" ::: "memory")
#define CP_WAIT(n)  asm volatile("cp.async.wait_group %0;" :: "n"(n) : "memory")

#define LDSM4(r0, r1, r2, r3, a) \
    asm volatile("ldmatrix.sync.aligned.m8n8.x4.shared.b16 {%0,%1,%2,%3}, [%4];" \
                 : "=r"(r0), "=r"(r1), "=r"(r2), "=r"(r3) : "r"(a))

__device__ __forceinline__ void mma16816(float* c, const uint32_t* a, uint32_t b0, uint32_t b1) {
    asm volatile(
        "mma.sync.aligned.m16n8k16.row.col.f32.f16.f16.f32 "
        "{%0,%1,%2,%3}, {%4,%5,%6,%7}, {%8,%9}, {%0,%1,%2,%3};"
        : "+f"(c[0]), "+f"(c[1]), "+f"(c[2]), "+f"(c[3])
        : "r"(a[0]), "r"(a[1]), "r"(a[2]), "r"(a[3]), "r"(b0), "r"(b1));
}

// ======================= level GEMM (single-term fp16 mma.sync) =======================
// out[M,256] = tanh(A[M,512] @ W[256,512]^T + bias), fp16 in/out, fp32 accum.
// CTA 128x128, 8 warps (4 M x 2 N), warp tile 32x64. KC=64 (8 chunks), 3-stage ring.
static constexpr int BM = 128, BN = 128, KC = 64;
static constexpr int NCH = 512 / KC;            // 8 chunks
static constexpr int RSTRIDE = 144;             // 128B data + 16B pad; ldsm conflict-free
static constexpr int TILE_B  = 128 * RSTRIDE;   // 18432 B
static constexpr int STAGE_B = 2 * TILE_B;      // A + W = 36864 B
static constexpr int NSTG = 3;
static constexpr int SMEM_BYTES = NSTG * STAGE_B;  // 110592 B -> 2 CTAs/SM

__device__ __forceinline__ uint32_t laddr(uint32_t S, int base_row, int ks, int lane) {
    return S + (uint32_t)(base_row + (lane & 15)) * RSTRIDE + ks * 32 + ((lane >> 4) << 4);
}

template <bool GATHER>
__global__ void __launch_bounds__(256, 2)
mma_level(const __half* __restrict__ Ain,
          const int* __restrict__ tokens,
          const float* __restrict__ bias, __half* __restrict__ Out) {
    extern __shared__ char sm[];
    __shared__ int stok[256];
    const uint32_t smb = smem_u32(sm);

    const int tid  = threadIdx.x;
    const int wid  = tid >> 5;
    const int lane = tid & 31;
    const int g    = lane >> 2;
    const int t    = lane & 3;
    const int m0 = (wid & 3) * 32;
    const int n0 = (wid >> 2) * 64;
    const int rowBase = blockIdx.x * BM;
    const int nBase   = blockIdx.y * BN;

    if (GATHER) {
        // tokens for this CTA's 128 rows: row r uses tok[2r + (col>=256)]
        int r = tid >> 1, j = tid & 1;
        int m = rowBase + r;
        stok[tid] = __ldg(&tokens[((m >> 8) << 9) + ((m & 255) << 1) + j]);
        __syncthreads();
    }

    // ---- chunk fill: A 1024 + W 1024 units of 16B, 8 per thread ----
    auto fill = [&](int c, int s) {
        const uint32_t sb = smb + s * STAGE_B;
#pragma unroll
        for (int i = 0; i < 4; ++i) {           // A units
            int o = tid + i * 256;              // 0..1023
            int r = o >> 3, u = o & 7;
            const void* src;
            if (GATHER) {
                int tok = stok[r * 2 + (c >> 2)];
                src = g_E + (size_t)tok * 256 + ((c & 3) * 64) + u * 8;
            } else {
                src = Ain + (size_t)(rowBase + r) * 512 + c * KC + u * 8;
            }
            cpa16(sb + r * RSTRIDE + u * 16, src);
        }
#pragma unroll
        for (int i = 0; i < 4; ++i) {           // W units
            int o = tid + i * 256;
            int r = o >> 3, u = o & 7;
            cpa16(sb + TILE_B + r * RSTRIDE + u * 16,
                  g_W + (size_t)(nBase + r) * 512 + c * KC + u * 8);
        }
        CP_COMMIT();
    };

    float acc[2][8][4];
#pragma unroll
    for (int mt = 0; mt < 2; ++mt)
#pragma unroll
        for (int nt = 0; nt < 8; ++nt)
#pragma unroll
            for (int j = 0; j < 4; ++j) acc[mt][nt][j] = 0.0f;

    fill(0, 0);
    fill(1, 1);

    for (int c = 0; c < NCH; ++c) {
        if (c < NCH - 1) { CP_WAIT(1); } else { CP_WAIT(0); }
        __syncthreads();
        if (c + 2 < NCH) fill(c + 2, (c + 2) % NSTG);

        const uint32_t SA = smb + (c % NSTG) * STAGE_B;
        const uint32_t SW = SA + TILE_B;

#pragma unroll
        for (int ks = 0; ks < 4; ++ks) {        // four k16 steps in KC=64
            uint32_t a[2][4];
            LDSM4(a[0][0], a[0][1], a[0][2], a[0][3], laddr(SA, m0,      ks, lane));
            LDSM4(a[1][0], a[1][1], a[1][2], a[1][3], laddr(SA, m0 + 16, ks, lane));
#pragma unroll
            for (int half = 0; half < 2; ++half) {
                uint32_t b[8];
                LDSM4(b[0], b[1], b[2], b[3], laddr(SW, n0 + half * 32,      ks, lane));
                LDSM4(b[4], b[5], b[6], b[7], laddr(SW, n0 + half * 32 + 16, ks, lane));
#pragma unroll
                for (int jj = 0; jj < 2; ++jj) {
#pragma unroll
                    for (int sub = 0; sub < 2; ++sub) {
                        const int nt = half * 4 + jj * 2 + sub;
                        const uint32_t b0 = b[jj * 4 + sub], b1 = b[jj * 4 + sub + 2];
                        mma16816(acc[0][nt], a[0], b0, b1);
                        mma16816(acc[1][nt], a[1], b0, b1);
                    }
                }
            }
        }
    }

    // ---- epilogue: +bias, tanh, fp16 store ----
#pragma unroll
    for (int mt = 0; mt < 2; ++mt) {
#pragma unroll
        for (int nt = 0; nt < 8; ++nt) {
            const int col = nBase + n0 + nt * 8 + 2 * t;
            const float b0 = __ldg(&bias[col]);
            const float b1 = __ldg(&bias[col + 1]);
#pragma unroll
            for (int h = 0; h < 2; ++h) {
                const int row = rowBase + m0 + mt * 16 + g + h * 8;
                float v0 = tanhf(acc[mt][nt][2 * h]     + b0);
                float v1 = tanhf(acc[mt][nt][2 * h + 1] + b1);
                *reinterpret_cast<__half2*>(Out + (size_t)row * 256 + col) =
                    __floats2half2_rn(v0, v1);
            }
        }
    }
}

// ======================= fp16 conversions (one-time) =======================
__global__ void __launch_bounds__(256)
weight_split(const float* __restrict__ W) {
    int i = blockIdx.x * 256 + threadIdx.x;        // 131072 elems
    g_W[i] = __float2half_rn(W[i]);
}
__global__ void __launch_bounds__(256)
embed_to_fp16(const float* __restrict__ E) {
    int base = (blockIdx.x * 256 + threadIdx.x) * 8;   // 8192000 elems total
    const float4* s = reinterpret_cast<const float4*>(E + base);
    float4 v0 = s[0], v1 = s[1];
    __half2 h0 = __floats2half2_rn(v0.x, v0.y);
    __half2 h1 = __floats2half2_rn(v0.z, v0.w);
    __half2 h2 = __floats2half2_rn(v1.x, v1.y);
    __half2 h3 = __floats2half2_rn(v1.z, v1.w);
    uint4 pk;
    pk.x = *reinterpret_cast<uint32_t*>(&h0);
    pk.y = *reinterpret_cast<uint32_t*>(&h1);
    pk.z = *reinterpret_cast<uint32_t*>(&h2);
    pk.w = *reinterpret_cast<uint32_t*>(&h3);
    *reinterpret_cast<uint4*>(g_E + base) = pk;
}

// ======================= head =======================
__global__ void __launch_bounds__(256)
head_kernel(const __half* __restrict__ root,      // [256, 256] fp16
            const float* __restrict__ WF, const float* __restrict__ bF,
            const float* __restrict__ WO, const float* __restrict__ bO,
            float* __restrict__ out) {
    __shared__ float r[256];
    __shared__ float h[256];
    int b = blockIdx.x, t = threadIdx.x;
    r[t] = __half2float(root[b * 256 + t]);
    __syncthreads();
    float acc = bF[t];
    const float* w = WF + (size_t)t * 256;
#pragma unroll 8
    for (int d = 0; d < 256; d += 4) {
        float4 w4 = *reinterpret_cast<const float4*>(w + d);
        acc += r[d] * w4.x + r[d + 1] * w4.y + r[d + 2] * w4.z + r[d + 3] * w4.w;
    }
    h[t] = fmaxf(acc, 0.0f);
    __syncthreads();
    int wid = t >> 5, lane = t & 31;
    if (wid < 5) {
        float s = 0.0f;
        for (int i = lane; i < 256; i += 32) s += h[i] * WO[wid * 256 + i];
#pragma unroll
        for (int o = 16; o; o >>= 1) s += __shfl_down_sync(0xffffffffu, s, o);
        if (lane == 0) out[b * 5 + wid] = s + bO[wid];
    }
}

// ======================= launch =======================
extern "C" void kernel_launch(void* const* d_in, const int* in_sizes, int n_in,
                              void* d_out, int out_size) {
    (void)in_sizes; (void)n_in; (void)out_size;
    const int*   tokens = (const int*)  d_in[0];
    const float* embed  = (const float*)d_in[1];
    const float* WR_w   = (const float*)d_in[2];
    const float* WR_b   = (const float*)d_in[3];
    const float* WF_w   = (const float*)d_in[4];
    const float* WF_b   = (const float*)d_in[5];
    const float* WO_w   = (const float*)d_in[6];
    const float* WO_b   = (const float*)d_in[7];
    float* out = (float*)d_out;

    cudaFuncSetAttribute(mma_level<true>,  cudaFuncAttributeMaxDynamicSharedMemorySize, SMEM_BYTES);
    cudaFuncSetAttribute(mma_level<false>, cudaFuncAttributeMaxDynamicSharedMemorySize, SMEM_BYTES);

    __half *A, *B;
    cudaGetSymbolAddress((void**)&A, g_A);
    cudaGetSymbolAddress((void**)&B, g_B);

    weight_split<<<512, 256>>>(WR_w);
    embed_to_fp16<<<4000, 256>>>(embed);           // 32000*256 / (256*8)

    // level 0: fused embedding gather (cp.async from fp16 table), out -> g_A
    {
        dim3 grid(65536 / BM, 2);
        mma_level<true><<<grid, 256, SMEM_BYTES>>>(nullptr, tokens, WR_b, A);
    }
    // levels 1..8: ping-pong  (odd: A->B, even: B->A)
    for (int lvl = 1; lvl <= 8; ++lvl) {
        int M = 65536 >> lvl;
        dim3 grid(M / BM, 2);
        const __half* in = (lvl & 1) ? A : B;
        __half*       ot = (lvl & 1) ? B : A;
        mma_level<false><<<grid, 256, SMEM_BYTES>>>(in, nullptr, WR_b, ot);
    }
    // root in g_A: [256, 256]
    head_kernel<<<256, 256>>>(A, WF_w, WF_b, WO_w, WO_b, out);
}